// round 14
// baseline (speedup 1.0000x reference)
#include <cuda_runtime.h>
#include <cuda_fp16.h>
#include <cstdint>

namespace qef {

constexpr int E_ = 8, T_ = 1024, DIN = 2048, DOUT = 8192;

// -------- scratch, fragment-ordered for mma.m16n8k16 --------
// B: [e][ntile(n/8)=1024][pair(64)][512B]  (32 lanes x 16B: {s0:b0,b1 | s1:b0,b1})
// A: [e][mtile(m/16)=64][ks16(128)][512B]  (32 lanes x 16B: {a0..a3})
__device__ __align__(16) unsigned char g_brep[(size_t)E_ * 1024 * 64 * 512];
__device__ __align__(16) unsigned char g_arep[(size_t)E_ * 64 * 128 * 512];

__device__ __forceinline__ uint32_t hpack(__half lo, __half hi) {
  return (uint32_t)__half_as_ushort(lo) | ((uint32_t)__half_as_ushort(hi) << 16);
}

// ---- fused repack: blocks [0,65536) do B, [65536,67584) do A ----------------
__global__ void __launch_bounds__(256) repack_all(const int* __restrict__ wq,
                                                  const float* __restrict__ in) {
  if (blockIdx.x < 65536) {
    const int t    = blockIdx.x * 256 + threadIdx.x;  // [0, 2^24)
    const int lane = t & 31;                          // nlo*4 + j
    const int nlo  = lane >> 2;
    const int j    = lane & 3;
    const int kc   = (t >> 5) & 63;                   // pair index (32 k)
    const int nhi  = (t >> 11) & 1023;
    const int e    = t >> 21;
    const int n    = nhi * 8 + nlo;
    const int* row = wq + ((size_t)e * DOUT + n) * DIN + kc * 32;
    const int2 p0 = *reinterpret_cast<const int2*>(row + 2 * j);
    const int2 p1 = *reinterpret_cast<const int2*>(row + 2 * j + 8);
    const int2 p2 = *reinterpret_cast<const int2*>(row + 2 * j + 16);
    const int2 p3 = *reinterpret_cast<const int2*>(row + 2 * j + 24);
    const uint32_t w0 = hpack(__int2half_rn(p0.x), __int2half_rn(p0.y));
    const uint32_t w1 = hpack(__int2half_rn(p1.x), __int2half_rn(p1.y));
    const uint32_t w2 = hpack(__int2half_rn(p2.x), __int2half_rn(p2.y));
    const uint32_t w3 = hpack(__int2half_rn(p3.x), __int2half_rn(p3.y));
    unsigned char* blk = g_brep + ((((size_t)e * 1024 + nhi) * 64 + kc) << 9);
    *reinterpret_cast<uint4*>(blk + lane * 16) = make_uint4(w0, w1, w2, w3);
  } else {
    const int t  = (blockIdx.x - 65536) * 256 + threadIdx.x;  // [0, 2^19)
    const int r  = t & 15;
    const int kc = (t >> 4) & 63;
    const int mt = (t >> 10) & 63;
    const int e  = t >> 16;
    const int m  = mt * 16 + r;
    const float4* src = reinterpret_cast<const float4*>(
        in + ((size_t)e * T_ + m) * DIN + kc * 32);
    __half h[32];
#pragma unroll
    for (int i = 0; i < 8; ++i) {
      float4 x4 = src[i];
      h[i * 4 + 0] = __float2half_rn(x4.x);
      h[i * 4 + 1] = __float2half_rn(x4.y);
      h[i * 4 + 2] = __float2half_rn(x4.z);
      h[i * 4 + 3] = __float2half_rn(x4.w);
    }
    const uint32_t lbase = (uint32_t)((r & 7) * 4) * 16 + ((r >= 8) ? 4u : 0u);
#pragma unroll
    for (int s = 0; s < 2; ++s) {
      unsigned char* blk = g_arep +
          ((((size_t)e * 64 + mt) * 128 + kc * 2 + s) << 9);
#pragma unroll
      for (int j = 0; j < 4; ++j) {
        const int kb = s * 16 + 2 * j;
        const uint32_t off = lbase + j * 16;
        *reinterpret_cast<uint32_t*>(blk + off)     = hpack(h[kb],     h[kb + 1]);
        *reinterpret_cast<uint32_t*>(blk + off + 8) = hpack(h[kb + 8], h[kb + 9]);
      }
    }
  }
}

// -- GEMM: CTA 128x128, 8 warps (4m x 2n), warp tile 32x64, 2 CTA/SM ---------
constexpr int A_STAGE = 8 * 4 * 512;       // 16KB: [mt(8)][kstep(4)] x 512B
constexpr int B_STAGE = 16 * 2 * 512;      // 16KB: [nt(16)][pair(2)] x 512B
constexpr int STAGE_BYTES = A_STAGE + B_STAGE;      // 32KB
constexpr int SMEM_TOTAL  = 3 * STAGE_BYTES;        // 96KB per CTA

__device__ __forceinline__ uint32_t cvta_smem(const void* p) {
  uint32_t a;
  asm("{ .reg .u64 t; cvta.to.shared.u64 t, %1; cvt.u32.u64 %0, t; }" : "=r"(a) : "l"(p));
  return a;
}
__device__ __forceinline__ void cp16(uint32_t sdst, const void* gsrc) {
  asm volatile("cp.async.cg.shared.global [%0], [%1], 16;" :: "r"(sdst), "l"(gsrc));
}
__device__ __forceinline__ void cp_commit() {
  asm volatile("cp.async.commit_group;" ::: "memory");
}
__device__ __forceinline__ void cp_wait1() {
  asm volatile("cp.async.wait_group 1;" ::: "memory");
}
__device__ __forceinline__ void lds128(uint32_t* r, uint32_t a) {
  asm volatile("ld.shared.v4.b32 {%0,%1,%2,%3}, [%4];"
               : "=r"(r[0]), "=r"(r[1]), "=r"(r[2]), "=r"(r[3]) : "r"(a));
}
__device__ __forceinline__ void lds64(uint32_t* r, uint32_t a) {
  asm volatile("ld.shared.v2.b32 {%0,%1}, [%2];" : "=r"(r[0]), "=r"(r[1]) : "r"(a));
}
__device__ __forceinline__ void hmma_f32(float* d, const uint32_t* a, const uint32_t* b) {
  asm volatile(
      "mma.sync.aligned.m16n8k16.row.col.f32.f16.f16.f32 "
      "{%0,%1,%2,%3}, {%4,%5,%6,%7}, {%8,%9}, {%0,%1,%2,%3};"
      : "+f"(d[0]), "+f"(d[1]), "+f"(d[2]), "+f"(d[3])
      : "r"(a[0]), "r"(a[1]), "r"(a[2]), "r"(a[3]), "r"(b[0]), "r"(b[1]));
}

__global__ void __launch_bounds__(256, 2)
gemm(const float* __restrict__ sc, float* __restrict__ out) {
  extern __shared__ unsigned char smem[];
  const uint32_t sbase = cvta_smem(smem);
  const int tid  = threadIdx.x;
  const int wid  = tid >> 5;
  const int lane = tid & 31;

  const int bid = blockIdx.x;         // ((e*64 + n)*8 + m)
  const int m   = bid & 7;            // 8 m-tiles of 128 (fast: share B in L2)
  const int n   = (bid >> 3) & 63;    // 64 n-tiles of 128
  const int e   = bid >> 9;

  const int wm = wid >> 1;            // 4 x 32 rows
  const int wn = wid & 1;             // 2 x 64 cols

  const unsigned char* abase = g_arep + (size_t)(e * 64 + m * 8) * 65536;
  const unsigned char* bbase = g_brep + (size_t)(e * 1024 + n * 16) * 32768;

  // cp.async per-thread affine addressing; unit = 16B. 256 threads:
  // A: 1024 units/stage (4 iters), B: 1024 units/stage (4 iters);
  // iter stride: gmem +131072B, smem +4096B for both.
  const unsigned char* pa;
  {
    const int chunk = tid >> 5;                 // mt(0..1)*4 + kstep(0..3)
    pa = abase + (size_t)(chunk >> 2) * 65536 + (chunk & 3) * 512 + (tid & 31) * 16;
  }
  const unsigned char* pb;
  {
    const int chunk = tid >> 5;                 // nt(0..3)*2 + pair
    pb = bbase + (size_t)(chunk >> 1) * 32768 + (chunk & 1) * 512 + (tid & 31) * 16;
  }
  const uint32_t sA0 = tid * 16;
  const uint32_t sB0 = A_STAGE + tid * 16;

  auto issue_stage = [&](int st) {
    const uint32_t sb = sbase + st * STAGE_BYTES;
#pragma unroll
    for (int i = 0; i < 4; ++i)
      cp16(sb + sA0 + i * 4096, pa + (size_t)i * 131072);
#pragma unroll
    for (int i = 0; i < 4; ++i)
      cp16(sb + sB0 + i * 4096, pb + (size_t)i * 131072);
    cp_commit();
    pa += 2048; pb += 1024;           // advance one K=64 stage
  };

  float acc[2][8][4];
#pragma unroll
  for (int mi = 0; mi < 2; ++mi)
#pragma unroll
    for (int ni = 0; ni < 8; ++ni)
#pragma unroll
      for (int c = 0; c < 4; ++c) acc[mi][ni][c] = 0.0f;

  const int NST = 32;   // 32 stages of K=64
  issue_stage(0);
  issue_stage(1);

  const uint32_t a_warp = ((uint32_t)wm * 2 * 4) * 512 + lane * 16;  // + (mi*4+kstep)*512
  const uint32_t b_warp = A_STAGE + ((uint32_t)wn * 8 * 2) * 512 + lane * 16;  // + (ni*2+pair)*512 + sk*8

  int cslot = 0, islot = 2;
  for (int ks = 0; ks < NST; ++ks) {
    cp_wait1();
    __syncthreads();
    // refill first: islot was consumed a full iteration ago; the copy overlaps
    // this stage's entire compute phase.
    if (ks + 2 < NST) {
      issue_stage(islot);
      if (++islot == 3) islot = 0;
    } else {
      cp_commit();    // uniform commit keeps wait_group accounting valid
    }
    const uint32_t sb = sbase + cslot * STAGE_BYTES;
    if (++cslot == 3) cslot = 0;

#pragma unroll
    for (int kstep = 0; kstep < 4; ++kstep) {
      const int pair = kstep >> 1, sk = kstep & 1;
      uint32_t af[2][4], bf[8][2];
#pragma unroll
      for (int mi = 0; mi < 2; ++mi)
        lds128(af[mi], sb + a_warp + (mi * 4 + kstep) * 512);
#pragma unroll
      for (int ni = 0; ni < 8; ++ni)
        lds64(bf[ni], sb + b_warp + (ni * 2 + pair) * 512 + sk * 8);
#pragma unroll
      for (int mi = 0; mi < 2; ++mi)
#pragma unroll
        for (int ni = 0; ni < 8; ++ni)
          hmma_f32(acc[mi][ni], af[mi], bf[ni]);
    }
  }

  // ---- epilogue: out = s * acc ----
  const float s = sc[e];
  const int r_in = lane >> 2;
  const int c_in = (lane & 3) * 2;
#pragma unroll
  for (int mi = 0; mi < 2; ++mi) {
    const int row0 = m * 128 + wm * 32 + mi * 16 + r_in;
#pragma unroll
    for (int ni = 0; ni < 8; ++ni) {
      const int col = n * 128 + wn * 64 + ni * 8 + c_in;
      const float* a = acc[mi][ni];
      float* o0 = out + ((size_t)e * T_ + row0) * DOUT + col;
      *reinterpret_cast<float2*>(o0)            = make_float2(a[0] * s, a[1] * s);
      *reinterpret_cast<float2*>(o0 + 8 * DOUT) = make_float2(a[2] * s, a[3] * s);
    }
  }
}

}  // namespace qef

extern "C" void kernel_launch(void* const* d_in, const int* in_sizes, int n_in,
                              void* d_out, int out_size) {
  const float* in  = (const float*)d_in[0];
  const int*   wq  = (const int*)d_in[1];
  const float* sc  = (const float*)d_in[2];
  float*       out = (float*)d_out;

  qef::repack_all<<<65536 + 2048, 256>>>(wq, in);

  static bool attr_set = false;
  if (!attr_set) {
    cudaFuncSetAttribute(qef::gemm, cudaFuncAttributeMaxDynamicSharedMemorySize,
                         qef::SMEM_TOTAL);
    attr_set = true;
  }
  qef::gemm<<<8 * 64 * 8, 256, qef::SMEM_TOTAL>>>(sc, out);
}

// round 15
// speedup vs baseline: 1.1293x; 1.1293x over previous
#include <cuda_runtime.h>
#include <cuda_fp16.h>
#include <cstdint>

namespace qef {

constexpr int E_ = 8, T_ = 1024, DIN = 2048, DOUT = 8192;

// -------- scratch, fragment-ordered for mma.m16n8k16 --------
// B: [e][ntile(n/8)=1024][pair(64)][512B]  (32 lanes x 16B: {s0:b0,b1 | s1:b0,b1})
// A: [e][mtile(m/16)=64][ks16(128)][512B]  (32 lanes x 16B: {a0..a3})
__device__ __align__(16) unsigned char g_brep[(size_t)E_ * 1024 * 64 * 512];
__device__ __align__(16) unsigned char g_arep[(size_t)E_ * 64 * 128 * 512];

__device__ __forceinline__ uint32_t hpack(__half lo, __half hi) {
  return (uint32_t)__half_as_ushort(lo) | ((uint32_t)__half_as_ushort(hi) << 16);
}

// ---- fused repack: blocks [0,65536) do B, [65536,67584) do A ----------------
__global__ void __launch_bounds__(256) repack_all(const int* __restrict__ wq,
                                                  const float* __restrict__ in) {
  if (blockIdx.x < 65536) {
    const int t    = blockIdx.x * 256 + threadIdx.x;  // [0, 2^24)
    const int lane = t & 31;                          // nlo*4 + j
    const int nlo  = lane >> 2;
    const int j    = lane & 3;
    const int kc   = (t >> 5) & 63;                   // pair index (32 k)
    const int nhi  = (t >> 11) & 1023;
    const int e    = t >> 21;
    const int n    = nhi * 8 + nlo;
    const int* row = wq + ((size_t)e * DOUT + n) * DIN + kc * 32;
    const int2 p0 = *reinterpret_cast<const int2*>(row + 2 * j);
    const int2 p1 = *reinterpret_cast<const int2*>(row + 2 * j + 8);
    const int2 p2 = *reinterpret_cast<const int2*>(row + 2 * j + 16);
    const int2 p3 = *reinterpret_cast<const int2*>(row + 2 * j + 24);
    const uint32_t w0 = hpack(__int2half_rn(p0.x), __int2half_rn(p0.y));
    const uint32_t w1 = hpack(__int2half_rn(p1.x), __int2half_rn(p1.y));
    const uint32_t w2 = hpack(__int2half_rn(p2.x), __int2half_rn(p2.y));
    const uint32_t w3 = hpack(__int2half_rn(p3.x), __int2half_rn(p3.y));
    unsigned char* blk = g_brep + ((((size_t)e * 1024 + nhi) * 64 + kc) << 9);
    *reinterpret_cast<uint4*>(blk + lane * 16) = make_uint4(w0, w1, w2, w3);
  } else {
    const int t  = (blockIdx.x - 65536) * 256 + threadIdx.x;  // [0, 2^19)
    const int r  = t & 15;
    const int kc = (t >> 4) & 63;
    const int mt = (t >> 10) & 63;
    const int e  = t >> 16;
    const int m  = mt * 16 + r;
    const float4* src = reinterpret_cast<const float4*>(
        in + ((size_t)e * T_ + m) * DIN + kc * 32);
    __half h[32];
#pragma unroll
    for (int i = 0; i < 8; ++i) {
      float4 x4 = src[i];
      h[i * 4 + 0] = __float2half_rn(x4.x);
      h[i * 4 + 1] = __float2half_rn(x4.y);
      h[i * 4 + 2] = __float2half_rn(x4.z);
      h[i * 4 + 3] = __float2half_rn(x4.w);
    }
    const uint32_t lbase = (uint32_t)((r & 7) * 4) * 16 + ((r >= 8) ? 4u : 0u);
#pragma unroll
    for (int s = 0; s < 2; ++s) {
      unsigned char* blk = g_arep +
          ((((size_t)e * 64 + mt) * 128 + kc * 2 + s) << 9);
#pragma unroll
      for (int j = 0; j < 4; ++j) {
        const int kb = s * 16 + 2 * j;
        const uint32_t off = lbase + j * 16;
        *reinterpret_cast<uint32_t*>(blk + off)     = hpack(h[kb],     h[kb + 1]);
        *reinterpret_cast<uint32_t*>(blk + off + 8) = hpack(h[kb + 8], h[kb + 9]);
      }
    }
  }
}

// -- GEMM: CTA 128x128, 4 warps (2m x 2n), warp 64x64, K=64 stages x3, 2 CTA/SM
// cp.async refills interleaved into the kstep loop (no serial copy prologue).
constexpr int A_STAGE = 8 * 4 * 512;       // 16KB: [mt(8)][kstep(4)] x 512B
constexpr int B_STAGE = 16 * 2 * 512;      // 16KB: [nt(16)][pair(2)] x 512B
constexpr int STAGE_BYTES = A_STAGE + B_STAGE;      // 32KB
constexpr int SMEM_TOTAL  = 3 * STAGE_BYTES;        // 96KB per CTA

__device__ __forceinline__ uint32_t cvta_smem(const void* p) {
  uint32_t a;
  asm("{ .reg .u64 t; cvta.to.shared.u64 t, %1; cvt.u32.u64 %0, t; }" : "=r"(a) : "l"(p));
  return a;
}
__device__ __forceinline__ void cp16(uint32_t sdst, const void* gsrc) {
  asm volatile("cp.async.cg.shared.global [%0], [%1], 16;" :: "r"(sdst), "l"(gsrc));
}
__device__ __forceinline__ void cp_commit() {
  asm volatile("cp.async.commit_group;" ::: "memory");
}
__device__ __forceinline__ void cp_wait1() {
  asm volatile("cp.async.wait_group 1;" ::: "memory");
}
__device__ __forceinline__ void lds128(uint32_t* r, uint32_t a) {
  asm volatile("ld.shared.v4.b32 {%0,%1,%2,%3}, [%4];"
               : "=r"(r[0]), "=r"(r[1]), "=r"(r[2]), "=r"(r[3]) : "r"(a));
}
__device__ __forceinline__ void hmma_f32(float* d, const uint32_t* a, const uint32_t* b) {
  asm volatile(
      "mma.sync.aligned.m16n8k16.row.col.f32.f16.f16.f32 "
      "{%0,%1,%2,%3}, {%4,%5,%6,%7}, {%8,%9}, {%0,%1,%2,%3};"
      : "+f"(d[0]), "+f"(d[1]), "+f"(d[2]), "+f"(d[3])
      : "r"(a[0]), "r"(a[1]), "r"(a[2]), "r"(a[3]), "r"(b[0]), "r"(b[1]));
}

__global__ void __launch_bounds__(128, 2)
gemm(const float* __restrict__ sc, float* __restrict__ out) {
  extern __shared__ unsigned char smem[];
  const uint32_t sbase = cvta_smem(smem);
  const int tid  = threadIdx.x;
  const int wid  = tid >> 5;
  const int lane = tid & 31;

  const int bid = blockIdx.x;         // ((e*64 + n)*8 + m)
  const int m   = bid & 7;            // 8 m-tiles of 128 (fast: share B in L2)
  const int n   = (bid >> 3) & 63;    // 64 n-tiles of 128
  const int e   = bid >> 9;

  const int wm = wid >> 1;            // 2 x 64 rows
  const int wn = wid & 1;             // 2 x 64 cols

  const unsigned char* abase = g_arep + (size_t)(e * 64 + m * 8) * 65536;
  const unsigned char* bbase = g_brep + (size_t)(e * 1024 + n * 16) * 32768;

  // cp.async per-thread affine addressing; unit = 16B. 128 threads:
  // A: 1024 units/stage (8 iters), gmem iter stride 65536B, smem 2048B.
  // B: 1024 units/stage (8 iters), gmem iter stride 65536B, smem 2048B.
  const unsigned char* pa;
  {
    const int kstep = (tid >> 5) & 3;
    pa = abase + kstep * 512 + (tid & 31) * 16;
  }
  const unsigned char* pb;
  {
    const int chunk = (tid >> 5) & 3;           // nt(0..1)*2 + pair
    pb = bbase + (size_t)(chunk >> 1) * 32768 + (chunk & 1) * 512 + (tid & 31) * 16;
  }
  const uint32_t sA0 = tid * 16;
  const uint32_t sB0 = A_STAGE + tid * 16;

  // serial issue only for the two prologue stages
  auto issue_stage = [&](int st) {
    const uint32_t sb = sbase + st * STAGE_BYTES;
#pragma unroll
    for (int i = 0; i < 8; ++i)
      cp16(sb + sA0 + i * 2048, pa + (size_t)i * 65536);
#pragma unroll
    for (int i = 0; i < 8; ++i)
      cp16(sb + sB0 + i * 2048, pb + (size_t)i * 65536);
    cp_commit();
    pa += 2048; pb += 1024;           // advance one K=64 stage
  };

  float acc[4][8][4];
#pragma unroll
  for (int mi = 0; mi < 4; ++mi)
#pragma unroll
    for (int ni = 0; ni < 8; ++ni)
#pragma unroll
      for (int c = 0; c < 4; ++c) acc[mi][ni][c] = 0.0f;

  const int NST = 32;   // 32 stages of K=64
  issue_stage(0);
  issue_stage(1);

  const uint32_t a_warp = ((uint32_t)wm * 4) * 2048 + lane * 16;      // +(mi*4+kstep)*512
  const uint32_t b_warp = A_STAGE + ((uint32_t)wn * 8) * 1024 + lane * 16;  // +ni*1024+pp*512

  int cslot = 0, islot = 2;
  for (int ks = 0; ks < NST; ++ks) {
    cp_wait1();
    __syncthreads();
    const uint32_t sb = sbase + cslot * STAGE_BYTES;
    if (++cslot == 3) cslot = 0;
    const bool refill = (ks + 2 < NST);
    const uint32_t ib = sbase + islot * STAGE_BYTES;
    if (refill && ++islot == 3) islot = 0;

#pragma unroll
    for (int pp = 0; pp < 2; ++pp) {
      uint32_t bf[8][4];
#pragma unroll
      for (int ni = 0; ni < 8; ++ni)
        lds128(bf[ni], sb + b_warp + ni * 1024 + pp * 512);
#pragma unroll
      for (int sk = 0; sk < 2; ++sk) {
        const int kstep = pp * 2 + sk;
        uint32_t af[4][4];
#pragma unroll
        for (int mi = 0; mi < 4; ++mi)
          lds128(af[mi], sb + a_warp + mi * 2048 + kstep * 512);
        // interleave 4 of the 16 refill copies into each kstep
        if (refill) {
#pragma unroll
          for (int i = 0; i < 2; ++i) {
            const int it = kstep * 2 + i;
            cp16(ib + sA0 + it * 2048, pa + (size_t)it * 65536);
            cp16(ib + sB0 + it * 2048, pb + (size_t)it * 65536);
          }
        }
#pragma unroll
        for (int mi = 0; mi < 4; ++mi)
#pragma unroll
          for (int ni = 0; ni < 8; ++ni)
            hmma_f32(acc[mi][ni], af[mi], &bf[ni][sk * 2]);
      }
    }
    // one commit per stage (uniform through the tail keeps wait accounting)
    cp_commit();
    if (refill) { pa += 2048; pb += 1024; }
  }

  // ---- epilogue: out = s * acc ----
  const float s = sc[e];
  const int r_in = lane >> 2;
  const int c_in = (lane & 3) * 2;
#pragma unroll
  for (int mi = 0; mi < 4; ++mi) {
    const int row0 = m * 128 + wm * 64 + mi * 16 + r_in;
#pragma unroll
    for (int ni = 0; ni < 8; ++ni) {
      const int col = n * 128 + wn * 64 + ni * 8 + c_in;
      const float* a = acc[mi][ni];
      float* o0 = out + ((size_t)e * T_ + row0) * DOUT + col;
      *reinterpret_cast<float2*>(o0)            = make_float2(a[0] * s, a[1] * s);
      *reinterpret_cast<float2*>(o0 + 8 * DOUT) = make_float2(a[2] * s, a[3] * s);
    }
  }
}

}  // namespace qef

extern "C" void kernel_launch(void* const* d_in, const int* in_sizes, int n_in,
                              void* d_out, int out_size) {
  const float* in  = (const float*)d_in[0];
  const int*   wq  = (const int*)d_in[1];
  const float* sc  = (const float*)d_in[2];
  float*       out = (float*)d_out;

  qef::repack_all<<<65536 + 2048, 256>>>(wq, in);

  static bool attr_set = false;
  if (!attr_set) {
    cudaFuncSetAttribute(qef::gemm, cudaFuncAttributeMaxDynamicSharedMemorySize,
                         qef::SMEM_TOTAL);
    attr_set = true;
  }
  qef::gemm<<<8 * 64 * 8, 128, qef::SMEM_TOTAL>>>(sc, out);
}